// round 11
// baseline (speedup 1.0000x reference)
#include <cuda_runtime.h>
#include <cuda_bf16.h>
#include <math_constants.h>
#include <cstdint>

#define HH 512
#define NH 32
#define LL 8192

// l = 32a + b.  K[h, 32a+b] = sum_n MR[a,n]*VR[n,b] - MI[a,n]*VI[n,b]
// Real GEMM per h: A[256 x 64] (k=2n -> MR, k=2n+1 -> MI) times B[64 x 32]
// (k=2n -> VR, k=2n+1 -> -VI).  M[a,n] = C2_n * w_n^(32a),  V[n,b] = w_n^b.

// Tables built by setup
__device__ float2 g_V  [HH * NH * NH];   // [h][b][n] = (VR, -VI)
__device__ float2 g_TWr[HH * NH * NH];   // [h][r][n] = w^(32 r)
__device__ float2 g_Mq [HH * 8  * NH];   // [h][q][n] = C2 * w^(1024 q)

// ---------------- helpers ----------------
static __device__ __forceinline__ float2 cmulf(float2 a, float2 b) {
    float2 r;
    r.x = fmaf(a.x, b.x, -(a.y * b.y));
    r.y = fmaf(a.x, b.y,  (a.y * b.x));
    return r;
}
static __device__ __forceinline__ float2 csqr(float2 a) {
    float2 r;
    r.x = fmaf(a.x, a.x, -(a.y * a.y));
    r.y = 2.0f * a.x * a.y;
    return r;
}
static __device__ __forceinline__ float2 bigpow(float dtar, float dtai, float p) {
    double u = (double)dtai * (double)p * (1.0 / CUDART_PI);
    double f = u - 2.0 * rint(u * 0.5);          // in [-1, 1]
    float s, c;
    sincospif((float)f, &s, &c);
    float mag = expf(dtar * p);                  // underflow to 0 == true answer
    return make_float2(mag * c, mag * s);
}
// pack complex (re, im) -> bf16x2 (re in low half) + residual pack
static __device__ __forceinline__ void bfsplit(float re, float im,
                                               uint32_t& p0, uint32_t& p1) {
    __nv_bfloat162 h0 = __float22bfloat162_rn(make_float2(re, im));
    float2 f0 = __bfloat1622float2(h0);
    __nv_bfloat162 h1 = __float22bfloat162_rn(make_float2(re - f0.x, im - f0.y));
    p0 = *reinterpret_cast<uint32_t*>(&h0);
    p1 = *reinterpret_cast<uint32_t*>(&h1);
}
static __device__ __forceinline__ void mma_bf16(float& c0, float& c1, float& c2, float& c3,
                                                uint32_t a0, uint32_t a1, uint32_t a2, uint32_t a3,
                                                uint32_t b0, uint32_t b1) {
    asm volatile(
        "mma.sync.aligned.m16n8k16.row.col.f32.bf16.bf16.f32 "
        "{%0,%1,%2,%3}, {%4,%5,%6,%7}, {%8,%9}, {%0,%1,%2,%3};"
        : "+f"(c0), "+f"(c1), "+f"(c2), "+f"(c3)
        : "r"(a0), "r"(a1), "r"(a2), "r"(a3), "r"(b0), "r"(b1));
}

// ---------------- Wide fused setup: thread per (h, n, i) ----------------
// idx = h*1024 + i*32 + n.  Each thread: recompute w (cheap, parallel),
// binary-power to V[i]=w^i and TWr[i]=(w^32)^i; i<8 also emits Mq anchor.
__global__ void __launch_bounds__(256) s4d_setup(const float* __restrict__ Cr,
                                                 const float* __restrict__ Ci,
                                                 const float* __restrict__ ldt,
                                                 const float* __restrict__ lar,
                                                 const float* __restrict__ Aim) {
    int idx = blockIdx.x * 256 + threadIdx.x;
    int n = idx & 31;
    int i = (idx >> 5) & 31;
    int h = idx >> 10;
    int hn = h * NH + n;

    // fp32 discretization, matching reference rounding
    float dtf  = expf(ldt[h]);
    float arf  = -expf(lar[hn]);
    float aif  = Aim[hn];
    float dtar = arf * dtf;
    float dtai = aif * dtf;

    float er, si, co;
    er = expf(dtar);
    sincosf(dtai, &si, &co);
    float2 w = make_float2(er * co, er * si);

    // V[i] = w^i via binary powering over squaring levels (in registers)
    {
        float2 x = w;
        float2 v = make_float2(1.0f, 0.0f);
        #pragma unroll
        for (int k = 0; k < 5; ++k) {
            if ((i >> k) & 1) v = cmulf(v, x);
            x = csqr(x);
        }
        g_V[h * (NH * NH) + i * NH + n] = make_float2(v.x, -v.y);   // (VR, -VI)
    }

    // TWr[i] = (w^32)^i from accurate anchor
    {
        float2 W = bigpow(dtar, dtai, 32.0f);
        float2 x = W;
        float2 t = make_float2(1.0f, 0.0f);
        #pragma unroll
        for (int k = 0; k < 5; ++k) {
            if ((i >> k) & 1) t = cmulf(t, x);
            x = csqr(x);
        }
        g_TWr[h * (NH * NH) + i * NH + n] = t;
    }

    // Mq[q=i] = C2 * w^(1024 i) for i < 8
    if (i < 8) {
        float nr = w.x - 1.0f, ni = w.y;
        float den = arf * arf + aif * aif;
        float inv = 1.0f / den;
        float fr = (nr * arf + ni * aif) * inv;
        float fi = (ni * arf - nr * aif) * inv;
        float cr = Cr[hn], ci = Ci[hn];
        float2 C2 = make_float2(2.0f * (cr * fr - ci * fi),
                                2.0f * (cr * fi + ci * fr));
        float2 J = bigpow(dtar, dtai, 1024.0f * (float)i);
        g_Mq[(h * 8 + i) * NH + n] = cmulf(C2, J);
    }
}

// ---------------- Main: mma.sync bf16, 3-pass split (unchanged from R10) ----------------
// Grid = HH*2 (h, half).  Block = 128 (4 warps).  Warp wid handles a-tiles
// T = 8*half + wid + 4*t', t' in {0,1} (16 rows each).
// B fragments staged in smem, frag-ordered: Bf[split][s][m][lane*2 + reg].
__global__ void __launch_bounds__(128) s4d_main(float* __restrict__ out) {
    __shared__ uint32_t Bf[2 * 4 * 4 * 64];     // 8 KB

    int h    = blockIdx.x >> 1;
    int half = blockIdx.x & 1;
    int tid  = threadIdx.x;
    int wid  = tid >> 5;
    int lane = tid & 31;
    int tig  = lane & 3;         // thread-in-group
    int g    = lane >> 2;        // group id

    // ---- build B fragment array (once per block) ----
    #pragma unroll
    for (int i = 0; i < 8; ++i) {
        int e  = tid + i * 128;          // 0..1023  (s, m, lane_t, reg)
        int s  = e >> 8;
        int m  = (e >> 6) & 3;
        int li = e & 63;
        int lt = li >> 1;
        int rg = li & 1;
        int n  = 8 * s + (lt & 3) + 4 * rg;
        int b  = 8 * m + (lt >> 2);
        float2 v = g_V[h * (NH * NH) + b * NH + n];   // (VR, -VI)
        uint32_t p0, p1;
        bfsplit(v.x, v.y, p0, p1);
        Bf[((0 * 4 + s) * 4 + m) * 64 + li] = p0;     // hi
        Bf[((1 * 4 + s) * 4 + m) * 64 + li] = p1;     // lo (residual)
    }
    __syncthreads();

    // ---- persist TWr for this lane's two rows x 8 modes ----
    int rl0 = ((wid & 1) << 4) + g;
    int rl1 = rl0 + 8;
    float2 tw0[8], tw1[8];
    #pragma unroll
    for (int j = 0; j < 8; ++j) {
        int n = tig + 4 * j;
        tw0[j] = g_TWr[h * (NH * NH) + rl0 * NH + n];
        tw1[j] = g_TWr[h * (NH * NH) + rl1 * NH + n];
    }

    #pragma unroll
    for (int tp = 0; tp < 2; ++tp) {
        int T = 8 * half + wid + 4 * tp;     // global a-tile (16 rows)
        int q = T >> 1;                      // a >> 5

        // ---- generate A fragments ----
        uint32_t A0[2][8], A1[2][8];
        #pragma unroll
        for (int j = 0; j < 8; ++j) {
            int n = tig + 4 * j;
            float2 mq = g_Mq[(h * 8 + q) * NH + n];
            float re0 = fmaf(mq.x, tw0[j].x, -(mq.y * tw0[j].y));
            float im0 = fmaf(mq.x, tw0[j].y,  (mq.y * tw0[j].x));
            bfsplit(re0, im0, A0[0][j], A1[0][j]);
            float re1 = fmaf(mq.x, tw1[j].x, -(mq.y * tw1[j].y));
            float im1 = fmaf(mq.x, tw1[j].y,  (mq.y * tw1[j].x));
            bfsplit(re1, im1, A0[1][j], A1[1][j]);
        }

        float acc[4][4];
        #pragma unroll
        for (int m = 0; m < 4; ++m)
            #pragma unroll
            for (int k = 0; k < 4; ++k) acc[m][k] = 0.0f;

        // ---- 3 passes: A0*B1, A1*B0, A0*B0 ----
        #pragma unroll
        for (int p = 0; p < 3; ++p) {
            int bsplit = (p == 0) ? 1 : 0;
            #pragma unroll
            for (int s = 0; s < 4; ++s) {
                uint32_t a0 = (p == 1) ? A1[0][2 * s]     : A0[0][2 * s];
                uint32_t a1 = (p == 1) ? A1[1][2 * s]     : A0[1][2 * s];
                uint32_t a2 = (p == 1) ? A1[0][2 * s + 1] : A0[0][2 * s + 1];
                uint32_t a3 = (p == 1) ? A1[1][2 * s + 1] : A0[1][2 * s + 1];
                #pragma unroll
                for (int m = 0; m < 4; ++m) {
                    uint2 bb = *reinterpret_cast<const uint2*>(
                        &Bf[((bsplit * 4 + s) * 4 + m) * 64 + lane * 2]);
                    mma_bf16(acc[m][0], acc[m][1], acc[m][2], acc[m][3],
                             a0, a1, a2, a3, bb.x, bb.y);
                }
            }
        }

        // ---- store ----
        float* oph = out + h * LL;
        #pragma unroll
        for (int m = 0; m < 4; ++m) {
            int bc = 8 * m + 2 * tig;
            __stcs((float2*)(oph + (16 * T + g) * NH + bc),
                   make_float2(acc[m][0], acc[m][1]));
            __stcs((float2*)(oph + (16 * T + g + 8) * NH + bc),
                   make_float2(acc[m][2], acc[m][3]));
        }
    }
}

extern "C" void kernel_launch(void* const* d_in, const int* in_sizes, int n_in,
                              void* d_out, int out_size) {
    const float* C_real     = (const float*)d_in[0];
    const float* C_imag     = (const float*)d_in[1];
    const float* log_dt     = (const float*)d_in[2];
    const float* log_a_real = (const float*)d_in[3];
    const float* A_imag     = (const float*)d_in[4];
    float* out = (float*)d_out;

    s4d_setup<<<HH * NH * NH / 256, 256>>>(C_real, C_imag, log_dt, log_a_real, A_imag);
    s4d_main<<<HH * 2, 128>>>(out);
}

// round 12
// speedup vs baseline: 1.5330x; 1.5330x over previous
#include <cuda_runtime.h>
#include <cuda_bf16.h>
#include <math_constants.h>
#include <cstdint>

#define HH 512
#define NH 32
#define LL 8192

// l = 32a + b.  K[h, 32a+b] = sum_n MR[a,n]*VR[n,b] - MI[a,n]*VI[n,b]
// Real GEMM per h: A[256 x 64] (k=2n -> MR, k=2n+1 -> MI) times B[64 x 32]
// (k=2n -> VR, k=2n+1 -> -VI).  M[a,n] = C2_n * w_n^(32a),  V[n,b] = w_n^b.

// Tables built by setup
__device__ float2 g_V  [HH * NH * NH];   // [h][b][n] = (VR, -VI)
__device__ float2 g_TWr[HH * NH * NH];   // [h][r][n] = w^(32 r)
__device__ float2 g_Mq [HH * 8  * NH];   // [h][q][n] = C2 * w^(1024 q)

// ---------------- helpers ----------------
static __device__ __forceinline__ float2 cmulf(float2 a, float2 b) {
    float2 r;
    r.x = fmaf(a.x, b.x, -(a.y * b.y));
    r.y = fmaf(a.x, b.y,  (a.y * b.x));
    return r;
}
static __device__ __forceinline__ float2 csqr(float2 a) {
    float2 r;
    r.x = fmaf(a.x, a.x, -(a.y * a.y));
    r.y = 2.0f * a.x * a.y;
    return r;
}

// w^p for large p, all-fp32 compensated phase reduction (no fp64).
// turns = dtai*p/(2pi); frac recovered to ~4e-8 turns via hi/lo split.
static __device__ __forceinline__ float2 fpow(float dtar, float dtai, float p) {
    constexpr double INV2PI = 0.159154943091895335768883763372514362;
    constexpr float c_hi = (float)INV2PI;
    constexpr float c_lo = (float)(INV2PI - (double)c_hi);
    float x  = dtai * p;
    float e  = fmaf(dtai, p, -x);            // exact product residual
    float y  = x * c_hi;
    float yr = fmaf(x, c_hi, -y);            // exact product residual
    float r  = yr + fmaf(x, c_lo, e * c_hi);
    float k  = rintf(y);
    float f  = (y - k) + r;                  // frac in turns (Sterbenz-exact sub)
    float s, c;
    sincospif(2.0f * f, &s, &c);
    float mag = expf(dtar * p);              // underflow to 0 == true answer
    return make_float2(mag * c, mag * s);
}

// pack complex (re, im) -> bf16x2 (re in low half) + residual pack
static __device__ __forceinline__ void bfsplit(float re, float im,
                                               uint32_t& p0, uint32_t& p1) {
    __nv_bfloat162 h0 = __float22bfloat162_rn(make_float2(re, im));
    float2 f0 = __bfloat1622float2(h0);
    __nv_bfloat162 h1 = __float22bfloat162_rn(make_float2(re - f0.x, im - f0.y));
    p0 = *reinterpret_cast<uint32_t*>(&h0);
    p1 = *reinterpret_cast<uint32_t*>(&h1);
}
static __device__ __forceinline__ void mma_bf16(float& c0, float& c1, float& c2, float& c3,
                                                uint32_t a0, uint32_t a1, uint32_t a2, uint32_t a3,
                                                uint32_t b0, uint32_t b1) {
    asm volatile(
        "mma.sync.aligned.m16n8k16.row.col.f32.bf16.bf16.f32 "
        "{%0,%1,%2,%3}, {%4,%5,%6,%7}, {%8,%9}, {%0,%1,%2,%3};"
        : "+f"(c0), "+f"(c1), "+f"(c2), "+f"(c3)
        : "r"(a0), "r"(a1), "r"(a2), "r"(a3), "r"(b0), "r"(b1));
}

// ---------------- Wide fused setup, all fp32: thread per (h, n, i) ----------------
__global__ void __launch_bounds__(256) s4d_setup(const float* __restrict__ Cr,
                                                 const float* __restrict__ Ci,
                                                 const float* __restrict__ ldt,
                                                 const float* __restrict__ lar,
                                                 const float* __restrict__ Aim) {
    int idx = blockIdx.x * 256 + threadIdx.x;
    int n = idx & 31;
    int i = (idx >> 5) & 31;
    int h = idx >> 10;
    int hn = h * NH + n;

    // fp32 discretization, matching reference rounding
    float dtf  = expf(ldt[h]);
    float arf  = -expf(lar[hn]);
    float aif  = Aim[hn];
    float dtar = arf * dtf;
    float dtai = aif * dtf;

    float er, si, co;
    er = expf(dtar);
    sincosf(dtai, &si, &co);
    float2 w = make_float2(er * co, er * si);

    // V[i] = w^i via binary powering (small powers; matches reference rounding)
    {
        float2 x = w;
        float2 v = make_float2(1.0f, 0.0f);
        #pragma unroll
        for (int k = 0; k < 5; ++k) {
            if ((i >> k) & 1) v = cmulf(v, x);
            x = csqr(x);
        }
        g_V[h * (NH * NH) + i * NH + n] = make_float2(v.x, -v.y);   // (VR, -VI)
    }

    // TWr[i] = w^(32 i) directly via compensated fp32 pow
    g_TWr[h * (NH * NH) + i * NH + n] = fpow(dtar, dtai, 32.0f * (float)i);

    // Mq[q=i] = C2 * w^(1024 i) for i < 8
    if (i < 8) {
        float nr = fmaf(er, co, -1.0f), ni = er * si;   // w - 1
        float den = arf * arf + aif * aif;
        float inv = 1.0f / den;
        float fr = (nr * arf + ni * aif) * inv;
        float fi = (ni * arf - nr * aif) * inv;
        float cr = Cr[hn], ci = Ci[hn];
        float2 C2 = make_float2(2.0f * (cr * fr - ci * fi),
                                2.0f * (cr * fi + ci * fr));
        float2 J = fpow(dtar, dtai, 1024.0f * (float)i);
        g_Mq[(h * 8 + i) * NH + n] = cmulf(C2, J);
    }
}

// ---------------- Main: mma.sync bf16, 3-pass split (unchanged from R10/R11) ----------------
__global__ void __launch_bounds__(128) s4d_main(float* __restrict__ out) {
    __shared__ uint32_t Bf[2 * 4 * 4 * 64];     // 8 KB

    int h    = blockIdx.x >> 1;
    int half = blockIdx.x & 1;
    int tid  = threadIdx.x;
    int wid  = tid >> 5;
    int lane = tid & 31;
    int tig  = lane & 3;         // thread-in-group
    int g    = lane >> 2;        // group id

    // ---- build B fragment array (once per block) ----
    #pragma unroll
    for (int i = 0; i < 8; ++i) {
        int e  = tid + i * 128;          // 0..1023  (s, m, lane_t, reg)
        int s  = e >> 8;
        int m  = (e >> 6) & 3;
        int li = e & 63;
        int lt = li >> 1;
        int rg = li & 1;
        int n  = 8 * s + (lt & 3) + 4 * rg;
        int b  = 8 * m + (lt >> 2);
        float2 v = g_V[h * (NH * NH) + b * NH + n];   // (VR, -VI)
        uint32_t p0, p1;
        bfsplit(v.x, v.y, p0, p1);
        Bf[((0 * 4 + s) * 4 + m) * 64 + li] = p0;     // hi
        Bf[((1 * 4 + s) * 4 + m) * 64 + li] = p1;     // lo (residual)
    }
    __syncthreads();

    // ---- persist TWr for this lane's two rows x 8 modes ----
    int rl0 = ((wid & 1) << 4) + g;
    int rl1 = rl0 + 8;
    float2 tw0[8], tw1[8];
    #pragma unroll
    for (int j = 0; j < 8; ++j) {
        int n = tig + 4 * j;
        tw0[j] = g_TWr[h * (NH * NH) + rl0 * NH + n];
        tw1[j] = g_TWr[h * (NH * NH) + rl1 * NH + n];
    }

    #pragma unroll
    for (int tp = 0; tp < 2; ++tp) {
        int T = 8 * half + wid + 4 * tp;     // global a-tile (16 rows)
        int q = T >> 1;                      // a >> 5

        // ---- generate A fragments ----
        uint32_t A0[2][8], A1[2][8];
        #pragma unroll
        for (int j = 0; j < 8; ++j) {
            int n = tig + 4 * j;
            float2 mq = g_Mq[(h * 8 + q) * NH + n];
            float re0 = fmaf(mq.x, tw0[j].x, -(mq.y * tw0[j].y));
            float im0 = fmaf(mq.x, tw0[j].y,  (mq.y * tw0[j].x));
            bfsplit(re0, im0, A0[0][j], A1[0][j]);
            float re1 = fmaf(mq.x, tw1[j].x, -(mq.y * tw1[j].y));
            float im1 = fmaf(mq.x, tw1[j].y,  (mq.y * tw1[j].x));
            bfsplit(re1, im1, A0[1][j], A1[1][j]);
        }

        float acc[4][4];
        #pragma unroll
        for (int m = 0; m < 4; ++m)
            #pragma unroll
            for (int k = 0; k < 4; ++k) acc[m][k] = 0.0f;

        // ---- 3 passes: A0*B1, A1*B0, A0*B0 ----
        #pragma unroll
        for (int p = 0; p < 3; ++p) {
            int bsplit = (p == 0) ? 1 : 0;
            #pragma unroll
            for (int s = 0; s < 4; ++s) {
                uint32_t a0 = (p == 1) ? A1[0][2 * s]     : A0[0][2 * s];
                uint32_t a1 = (p == 1) ? A1[1][2 * s]     : A0[1][2 * s];
                uint32_t a2 = (p == 1) ? A1[0][2 * s + 1] : A0[0][2 * s + 1];
                uint32_t a3 = (p == 1) ? A1[1][2 * s + 1] : A0[1][2 * s + 1];
                #pragma unroll
                for (int m = 0; m < 4; ++m) {
                    uint2 bb = *reinterpret_cast<const uint2*>(
                        &Bf[((bsplit * 4 + s) * 4 + m) * 64 + lane * 2]);
                    mma_bf16(acc[m][0], acc[m][1], acc[m][2], acc[m][3],
                             a0, a1, a2, a3, bb.x, bb.y);
                }
            }
        }

        // ---- store ----
        float* oph = out + h * LL;
        #pragma unroll
        for (int m = 0; m < 4; ++m) {
            int bc = 8 * m + 2 * tig;
            __stcs((float2*)(oph + (16 * T + g) * NH + bc),
                   make_float2(acc[m][0], acc[m][1]));
            __stcs((float2*)(oph + (16 * T + g + 8) * NH + bc),
                   make_float2(acc[m][2], acc[m][3]));
        }
    }
}

extern "C" void kernel_launch(void* const* d_in, const int* in_sizes, int n_in,
                              void* d_out, int out_size) {
    const float* C_real     = (const float*)d_in[0];
    const float* C_imag     = (const float*)d_in[1];
    const float* log_dt     = (const float*)d_in[2];
    const float* log_a_real = (const float*)d_in[3];
    const float* A_imag     = (const float*)d_in[4];
    float* out = (float*)d_out;

    s4d_setup<<<HH * NH * NH / 256, 256>>>(C_real, C_imag, log_dt, log_a_real, A_imag);
    s4d_main<<<HH * 2, 128>>>(out);
}